// round 6
// baseline (speedup 1.0000x reference)
#include <cuda_runtime.h>

// MedianFilter: xs [B=4,T=32,N=128,D=32] f32, A [1,128,128] i32.
// Per (b,t,n,d): lower median over {prev-self (t>0), next-self (t<T-1),
//   xs[b,t,j,d] for j with (A+I)[n][j]!=0}.
// Exact MSB-first radix-select. Scan1: unfiltered nibble hist @28 (dual
// accumulators). Collect byte-indices of g1-matchers (avg ~33). Scan2:
// unfiltered nibble hist @24 over compacted indices. Compact to ~2-3, tiny
// radix tail via index reload. Masked/pad candidates are 0xFFFFFFFF keys
// (== reference's +inf padding), counted uniformly; rank m < true k keeps
// selection exact.

#define Bc 4
#define Tc 32
#define Nc 128
#define Dc 32
#define NTH 512          // 16 warps, 1 warp = 1 node
#define NODES_PB 16
#define CAP1 48          // byte-index buffer slots
#define ROWP 132
#define DUMMY_ROW 128
#define TROWS 161        // 128 data + dummy + 16 prev + 16 next

typedef unsigned long long u64;

__device__ unsigned char g_nbr[Nc * ROWP];
__device__ int g_cnt[Nc];

__device__ __forceinline__ unsigned f2u(float f) {
    unsigned s = __float_as_uint(f);
    return s ^ ((unsigned)((int)s >> 31) | 0x80000000u);
}
__device__ __forceinline__ float u2f(unsigned u) {
    unsigned s = (u & 0x80000000u) ? (u ^ 0x80000000u) : ~u;
    return __uint_as_float(s);
}

// bin containing rank m from byte-packed histograms B0(bins0-7)/B1(8-15);
// total <= ~135 so bytes never overflow. m -> within-bin rank; rem = count.
__device__ __forceinline__ int select_bin(u64 B0, u64 B1,
                                          unsigned &m, unsigned &rem)
{
    u64 s0 = B0 * 0x0101010101010101ull;
    unsigned tot0 = (unsigned)(s0 >> 56);
    u64 S, H;
    int base;
    unsigned mm = m;
    if (mm < tot0) { S = s0; H = B0; base = 0; }
    else { mm -= tot0; S = B1 * 0x0101010101010101ull; H = B1; base = 8; }
    int g = 0;
    if ((unsigned)((S >> 24) & 0xFF) <= mm) g = 4;
    if ((unsigned)((S >> (8 * (g + 1))) & 0xFF) <= mm) g += 2;
    if ((unsigned)((S >> (8 * g)) & 0xFF) <= mm) g += 1;
    unsigned before = g ? (unsigned)((S >> (8 * (g - 1))) & 0xFF) : 0u;
    rem = (unsigned)((H >> (8 * g)) & 0xFF);
    m = mm - before;
    return base + g;
}

// expand nibble-packed h (16 x 4-bit) into byte-packed B0/B1
#define FLUSH(h_, B0_, B1_)                                                  \
    {                                                                        \
        unsigned lo_ = (unsigned)(h_), hi_ = (unsigned)((h_) >> 32);         \
        unsigned e0_ = lo_ & 0x0F0F0F0Fu, o0_ = (lo_ >> 4) & 0x0F0F0F0Fu;    \
        unsigned e1_ = hi_ & 0x0F0F0F0Fu, o1_ = (hi_ >> 4) & 0x0F0F0F0Fu;    \
        B0_ += ((u64)__byte_perm(e0_, o0_, 0x7362) << 32) |                  \
               (u64)__byte_perm(e0_, o0_, 0x5140);                           \
        B1_ += ((u64)__byte_perm(e1_, o1_, 0x7362) << 32) |                  \
               (u64)__byte_perm(e1_, o1_, 0x5140);                           \
    }

// filtered byte-packed hist (fallback only)
#define HISTF(u_)                                                            \
    {                                                                        \
        unsigned uu_ = (u_);                                                 \
        bool ma_ = ((uu_ ^ prefix) >> (shift + 4)) == 0u;                    \
        unsigned nib_ = (uu_ >> shift) & 15u;                                \
        u64 inc_ = ma_ ? (1ull << ((nib_ & 7u) * 8u)) : 0ull;                \
        if (nib_ & 8u) B1 += inc_; else B0 += inc_;                          \
    }

__global__ void prep_kernel(const int* __restrict__ A)
{
    __shared__ int wcnt[4];
    const int n = blockIdx.x;
    const int j = threadIdx.x;
    const int w = j >> 5, lane = j & 31;
    bool v = (A[n * Nc + j] != 0) || (j == n);
    unsigned mask = __ballot_sync(0xFFFFFFFFu, v);
    if (lane == 0) wcnt[w] = __popc(mask);
    __syncthreads();
    int base = 0;
    for (int i = 0; i < w; i++) base += wcnt[i];
    int off = base + __popc(mask & ((1u << lane) - 1u));
    if (v) g_nbr[n * ROWP + off] = (unsigned char)j;
    int tot = wcnt[0] + wcnt[1] + wcnt[2] + wcnt[3];
    if (j == 0) g_cnt[n] = tot;
    int padded = (tot + 3) & ~3;
    if (j >= tot && j < padded) g_nbr[n * ROWP + j] = (unsigned char)DUMMY_ROW;
}

extern __shared__ unsigned char ibuf[];   // CAP1 * NTH bytes = 24KB

__global__ __launch_bounds__(NTH, 3)
void median_kernel(const float* __restrict__ xs, float* __restrict__ out)
{
    __shared__ unsigned tile[TROWS * Dc];            // ~20.1KB
    __shared__ unsigned char nbr[NODES_PB * ROWP];   // 2.1KB
    __shared__ int cnt[NODES_PB];

    const int bid  = blockIdx.x;
    const int bt   = bid >> 3;
    const int oct  = bid & 7;
    const int t    = bt & (Tc - 1);
    const int tid  = threadIdx.x;
    const int lane = tid & 31;
    const int w    = tid >> 5;            // warp = local node
    const int n    = oct * NODES_PB + w;

    const float* cur = xs + (size_t)bt * (Nc * Dc);
    #pragma unroll
    for (int i = tid; i < Nc * Dc; i += NTH) tile[i] = f2u(cur[i]);
    if (tid < Dc) tile[DUMMY_ROW * Dc + tid] = 0xFFFFFFFFu;

    {
        const unsigned* src = (const unsigned*)&g_nbr[(oct * NODES_PB) * ROWP];
        unsigned* dst = (unsigned*)nbr;
        #pragma unroll
        for (int i = tid; i < NODES_PB * ROWP / 4; i += NTH) dst[i] = src[i];
        if (tid < NODES_PB) cnt[tid] = g_cnt[oct * NODES_PB + tid];
    }
    __syncthreads();

    const bool hasPrev = (t > 0);
    const bool hasNext = (t < Tc - 1);
    unsigned prevU = 0xFFFFFFFFu, nextU = 0xFFFFFFFFu;
    if (hasPrev) prevU = f2u(xs[(size_t)(bt - 1) * (Nc * Dc) + n * Dc + lane]);
    if (hasNext) nextU = f2u(xs[(size_t)(bt + 1) * (Nc * Dc) + n * Dc + lane]);
    const int PR = 129 + w, NR = 145 + w;       // private ext rows
    tile[(PR << 5) | lane] = prevU;             // same-thread write/read only
    tile[(NR << 5) | lane] = nextU;

    const int k  = cnt[w];
    const int kq = (k + 3) >> 2;
    const unsigned* lstw = (const unsigned*)&nbr[w * ROWP];
    unsigned m = (unsigned)((k + (int)hasPrev + (int)hasNext - 1) >> 1);
    unsigned rem;

    // ---------- scan 1: unfiltered nibble hist @28, dual accumulators ------
    unsigned g1;
    {
        u64 B0 = 0ull, B1 = 0ull;
        u64 ha = (1ull << ((prevU >> 26) & 0x3Cu))
               + (1ull << ((nextU >> 26) & 0x3Cu));
        u64 hb = 0ull;
        int q = 0;
        while (q < kq) {
            int qe = min(q + 6, kq);     // 24 adds/chunk, 12+2 per acc <= 15
            for (; q < qe; q++) {
                unsigned w4 = lstw[q];
                unsigned u0 = tile[((w4 & 255u) << 5) | lane];
                unsigned u1 = tile[(((w4 >> 8) & 255u) << 5) | lane];
                unsigned u2 = tile[(((w4 >> 16) & 255u) << 5) | lane];
                unsigned u3 = tile[((w4 >> 24) << 5) | lane];
                ha += 1ull << ((u0 >> 26) & 0x3Cu);
                hb += 1ull << ((u1 >> 26) & 0x3Cu);
                ha += 1ull << ((u2 >> 26) & 0x3Cu);
                hb += 1ull << ((u3 >> 26) & 0x3Cu);
            }
            FLUSH(ha, B0, B1);
            FLUSH(hb, B0, B1);
            ha = 0ull; hb = 0ull;
        }
        g1 = (unsigned)select_bin(B0, B1, m, rem);
    }

    // ---------- collect byte-indices of g1-matchers ----------
    int c1 = 0;
    for (int q = 0; q < kq; q++) {
        unsigned w4 = lstw[q];
        #pragma unroll
        for (int s = 0; s < 4; s++) {
            unsigned idx = (w4 >> (8 * s)) & 255u;
            unsigned u = tile[(idx << 5) | lane];
            if ((u >> 28) == g1) {
                if (c1 < CAP1) ibuf[c1 * NTH + tid] = (unsigned char)idx;
                c1++;
            }
        }
    }
    if ((prevU >> 28) == g1) { if (c1 < CAP1) ibuf[c1 * NTH + tid] = (unsigned char)PR; c1++; }
    if ((nextU >> 28) == g1) { if (c1 < CAP1) ibuf[c1 * NTH + tid] = (unsigned char)NR; c1++; }

    unsigned result = 0;
    const bool ovf = (c1 > CAP1);

    if (__any_sync(0xFFFFFFFFu, ovf)) {
        // ---- exact cold fallback: filtered full scans below nibble @28 ----
        if (ovf) {
            const unsigned char* lst = (const unsigned char*)lstw;
            unsigned prefix = g1 << 28;
            bool done = false;
            #pragma unroll 1
            for (int p = 1; p < 8 && !done; p++) {
                const int shift = 28 - 4 * p;
                u64 B0 = 0ull, B1 = 0ull;
                for (int i = 0; i < k; i++) {
                    unsigned u = tile[(((unsigned)lst[i]) << 5) | lane];
                    HISTF(u);
                }
                HISTF(prevU);
                HISTF(nextU);
                int g = select_bin(B0, B1, m, rem);
                prefix |= (unsigned)g << shift;
                if (rem == 1u) {
                    unsigned r = prefix;
                    for (int i = 0; i < k; i++) {
                        unsigned u = tile[(((unsigned)lst[i]) << 5) | lane];
                        if (((u ^ prefix) >> shift) == 0u) r = u;
                    }
                    if (((prevU ^ prefix) >> shift) == 0u) r = prevU;
                    if (((nextU ^ prefix) >> shift) == 0u) r = nextU;
                    result = r;
                    done = true;
                }
            }
            if (!done) result = prefix;
        }
    }

    // ---------- scan 2: unfiltered nibble hist @24 over compacted ----------
    int c2 = 1;                   // default for ovf / c1==1 lanes
    if (!ovf && c1 > 1) {
        u64 B0 = 0ull, B1 = 0ull;
        int i = 0;
        while (i < c1) {
            int ie = min(i + 28, c1);     // 14+14 per acc <= 15
            u64 ha = 0ull, hb = 0ull;
            for (; i + 1 < ie; i += 2) {
                unsigned ua = tile[(((unsigned)ibuf[i * NTH + tid]) << 5) | lane];
                unsigned ub = tile[(((unsigned)ibuf[(i + 1) * NTH + tid]) << 5) | lane];
                ha += 1ull << ((ua >> 22) & 0x3Cu);
                hb += 1ull << ((ub >> 22) & 0x3Cu);
            }
            if (i < ie) {
                unsigned ua = tile[(((unsigned)ibuf[i * NTH + tid]) << 5) | lane];
                ha += 1ull << ((ua >> 22) & 0x3Cu);
                i++;
            }
            FLUSH(ha, B0, B1);
            FLUSH(hb, B0, B1);
        }
        unsigned g2 = (unsigned)select_bin(B0, B1, m, rem);

        // compact indices matching nibble @24
        int cc = 0;
        for (int i2 = 0; i2 < c1; i2++) {
            unsigned idx = ibuf[i2 * NTH + tid];
            unsigned u = tile[(idx << 5) | lane];
            if (((u >> 24) & 15u) == g2) { ibuf[cc * NTH + tid] = (unsigned char)idx; cc++; }
        }
        c2 = cc;
    }

    // ---------- radix tail over c2 indices (all lanes traverse loop) -------
    int shift = 20;
    #pragma unroll 1
    while (__any_sync(0xFFFFFFFFu, !ovf && c2 > 1) && shift >= 0) {
        if (!ovf && c2 > 1) {
            u64 B0 = 0ull, B1 = 0ull;
            for (int i = 0; i < c2; i++) {
                unsigned u = tile[(((unsigned)ibuf[i * NTH + tid]) << 5) | lane];
                unsigned nib = (u >> shift) & 15u;
                u64 inc = 1ull << ((nib & 7u) * 8u);
                if (nib & 8u) B1 += inc; else B0 += inc;
            }
            int g = select_bin(B0, B1, m, rem);
            int cc = 0;
            for (int i = 0; i < c2; i++) {
                unsigned idx = ibuf[i * NTH + tid];
                unsigned u = tile[(idx << 5) | lane];
                if (((u >> shift) & 15u) == (unsigned)g) { ibuf[cc * NTH + tid] = (unsigned char)idx; cc++; }
            }
            c2 = cc;
        }
        shift -= 4;
    }
    if (!ovf) result = tile[(((unsigned)ibuf[tid]) << 5) | lane];

    out[(size_t)bt * (Nc * Dc) + n * Dc + lane] = u2f(result);
}

extern "C" void kernel_launch(void* const* d_in, const int* in_sizes, int n_in,
                              void* d_out, int out_size)
{
    const float* xs  = (const float*)d_in[0];
    const int*   A   = (const int*)d_in[1];
    float*       out = (float*)d_out;
    (void)in_sizes; (void)n_in; (void)out_size;

    cudaFuncSetAttribute(median_kernel,
                         cudaFuncAttributeMaxDynamicSharedMemorySize,
                         CAP1 * NTH);
    prep_kernel<<<Nc, Nc>>>(A);
    median_kernel<<<Bc * Tc * 8, NTH, CAP1 * NTH>>>(xs, out);
}

// round 7
// speedup vs baseline: 2.6816x; 2.6816x over previous
#include <cuda_runtime.h>

// MedianFilter: xs [B=4,T=32,N=128,D=32] f32, A [1,128,128] i32.
// Per (b,t,n,d): lower median over {prev-self (t>0), next-self (t<T-1),
//   xs[b,t,j,d] for j with (A+I)[n][j]!=0}.
//
// Shared-sort + bitmask rank selection (exact):
//  Per (bt, channel d): sort the 128 frame values once (bitonic, one warp per
//  channel, carrying original row index) and build cum[i] = 128-bit mask of
//  rows at sorted positions < i.  Per node: rank counts are popc(B_n & cum[i]),
//  so selecting the median is a 7-step binary search; temporal prev/next are
//  ranked via two value binary-searches.  Consistent total-order tie-breaking
//  makes the selected VALUE exact for any input (duplicates included).

#define Bc 4
#define Tc 32
#define Nc 128
#define Dc 32
#define NTH 1024

typedef unsigned u32;

// dynamic smem layout (words):
//  [0, 16512)      cum: per-channel stride 516 words (129 x uint4)   64.5KB
//                  (phase0 aliases this region as the value tile, 128x33 words)
//  [16512, 20640)  sorted keys: per-channel stride 129 words          16.5KB
//  [20640, 21152)  Bmask: 128 x uint4                                  2KB
extern __shared__ u32 smem[];
#define SORT_BASE 16512
#define BM_BASE   20640

__device__ __forceinline__ u32 f2u(float f) {
    u32 s = __float_as_uint(f);
    return s ^ ((u32)((int)s >> 31) | 0x80000000u);
}
__device__ __forceinline__ float u2f(u32 u) {
    u32 s = (u & 0x80000000u) ? (u ^ 0x80000000u) : ~u;
    return __uint_as_float(s);
}

// # members of B with value <= v  (members = spatial rows; channel ch)
__device__ __forceinline__ int cnt_le(int ch, u32 v, uint4 B) {
    int ub = 0;                      // count of sorted positions with key <= v
    #pragma unroll
    for (int st = 128; st > 0; st >>= 1) {
        int c = ub + st;
        if (c <= 128 && smem[SORT_BASE + ch * 129 + (c - 1)] <= v) ub = c;
    }
    const uint4 cm = *((const uint4*)(smem + ch * 516 + ub * 4));
    return __popc(B.x & cm.x) + __popc(B.y & cm.y)
         + __popc(B.z & cm.z) + __popc(B.w & cm.w);
}

__global__ __launch_bounds__(NTH, 1)
void median_kernel(const float* __restrict__ xs,
                   const int* __restrict__ A,
                   float* __restrict__ out)
{
    const int bt   = blockIdx.x;
    const int t    = bt & (Tc - 1);
    const int tid  = threadIdx.x;
    const int lane = tid & 31;
    const int w    = tid >> 5;        // phases 0/1: w = channel d; phase 2: warp id

    // ---------------- phase 0: value tile + membership masks ----------------
    const float* cur = xs + (size_t)bt * (Nc * Dc);
    #pragma unroll
    for (int i = tid; i < Nc * Dc; i += NTH) {
        int j = i >> 5, d = i & 31;
        smem[j * 33 + d] = f2u(cur[i]);          // tile aliased over cum region
    }
    if (tid < 512) {                              // Bmask: 4 threads per node
        int n = tid >> 2, ww = tid & 3;
        const int* ar = A + n * Nc + ww * 32;
        u32 b = 0;
        #pragma unroll 8
        for (int jj = 0; jj < 32; jj++) b |= (ar[jj] != 0 ? 1u : 0u) << jj;
        if ((n >> 5) == ww) b |= 1u << (n & 31);  // + I (self loop)
        smem[BM_BASE + n * 4 + ww] = b;
    }
    __syncthreads();

    // ---------------- phase 1: per-channel sort + cum masks -----------------
    // warp w sorts channel d = w; element at position p = r*32+lane.
    u32 k[4], xi[4];
    #pragma unroll
    for (int r = 0; r < 4; r++) {
        int p = r * 32 + lane;
        k[r]  = smem[p * 33 + w];
        xi[r] = (u32)p;                            // original row index
    }
    __syncthreads();    // all tile reads done before cum overwrites the region

    // bitonic sort ascending by key, carrying original index
    #pragma unroll
    for (int size = 2; size <= 128; size <<= 1) {
        #pragma unroll
        for (int stride = size >> 1; stride > 0; stride >>= 1) {
            if (stride >= 32) {
                int sr = stride >> 5;
                #pragma unroll
                for (int r = 0; r < 4; r++) {
                    if (!(r & sr)) {
                        int r2 = r | sr;
                        bool up = (((r * 32) & size) == 0);
                        if ((k[r] > k[r2]) == up) {
                            u32 tk = k[r]; k[r] = k[r2]; k[r2] = tk;
                            u32 tx = xi[r]; xi[r] = xi[r2]; xi[r2] = tx;
                        }
                    }
                }
            } else {
                #pragma unroll
                for (int r = 0; r < 4; r++) {
                    u32 p = (u32)(r * 32 + lane);
                    bool up    = ((p & (u32)size) == 0);
                    bool lower = ((lane & stride) == 0);
                    u32 pk = __shfl_xor_sync(0xFFFFFFFFu, k[r],  stride);
                    u32 px = __shfl_xor_sync(0xFFFFFFFFu, xi[r], stride);
                    bool take = (lower == up) ? (pk < k[r]) : (pk > k[r]);
                    if (take) { k[r] = pk; xi[r] = px; }
                }
            }
        }
    }

    // write sorted keys (per-channel stride 129 -> conflict-free in phase 2)
    #pragma unroll
    for (int r = 0; r < 4; r++)
        smem[SORT_BASE + w * 129 + r * 32 + lane] = k[r];

    // cum[i] = OR of onehot(orig row) over sorted positions < i
    u32 run0 = 0, run1 = 0, run2 = 0, run3 = 0;
    #pragma unroll
    for (int r = 0; r < 4; r++) {
        int ws = (int)(xi[r] >> 5);
        u32 bit = 1u << (xi[r] & 31u);
        u32 o0 = (ws == 0) ? bit : 0u, o1 = (ws == 1) ? bit : 0u;
        u32 o2 = (ws == 2) ? bit : 0u, o3 = (ws == 3) ? bit : 0u;
        #pragma unroll
        for (int s = 1; s < 32; s <<= 1) {
            u32 t0 = __shfl_up_sync(0xFFFFFFFFu, o0, s);
            u32 t1 = __shfl_up_sync(0xFFFFFFFFu, o1, s);
            u32 t2 = __shfl_up_sync(0xFFFFFFFFu, o2, s);
            u32 t3 = __shfl_up_sync(0xFFFFFFFFu, o3, s);
            if (lane >= s) { o0 |= t0; o1 |= t1; o2 |= t2; o3 |= t3; }
        }
        u32 e0 = __shfl_up_sync(0xFFFFFFFFu, o0, 1);
        u32 e1 = __shfl_up_sync(0xFFFFFFFFu, o1, 1);
        u32 e2 = __shfl_up_sync(0xFFFFFFFFu, o2, 1);
        u32 e3 = __shfl_up_sync(0xFFFFFFFFu, o3, 1);
        if (lane == 0) { e0 = 0; e1 = 0; e2 = 0; e3 = 0; }
        int p = r * 32 + lane;
        ((uint4*)(smem + w * 516 + p * 4))[0] =
            make_uint4(run0 | e0, run1 | e1, run2 | e2, run3 | e3);
        run0 |= __shfl_sync(0xFFFFFFFFu, o0, 31);
        run1 |= __shfl_sync(0xFFFFFFFFu, o1, 31);
        run2 |= __shfl_sync(0xFFFFFFFFu, o2, 31);
        run3 |= __shfl_sync(0xFFFFFFFFu, o3, 31);
    }
    if (lane == 0)
        ((uint4*)(smem + w * 516 + 128 * 4))[0] =
            make_uint4(~0u, ~0u, ~0u, ~0u);
    __syncthreads();

    // ---------------- phase 2: per-node median selection --------------------
    // warp w handles nodes w, w+32, w+64, w+96; lane = channel d.
    const bool hasPrev = (t > 0);
    const bool hasNext = (t < Tc - 1);

    #pragma unroll 1
    for (int nn = 0; nn < 4; nn++) {
        const int n = w + nn * 32;

        u32 prevU = 0xFFFFFFFFu, nextU = 0xFFFFFFFFu;
        if (hasPrev) prevU = f2u(xs[(size_t)(bt - 1) * (Nc * Dc) + n * Dc + lane]);
        if (hasNext) nextU = f2u(xs[(size_t)(bt + 1) * (Nc * Dc) + n * Dc + lane]);

        const uint4 B = *((const uint4*)(smem + BM_BASE + n * 4));   // broadcast
        const int kpop = __popc(B.x) + __popc(B.y) + __popc(B.z) + __popc(B.w);
        const int ktot = kpop + (int)hasPrev + (int)hasNext;
        const int m    = (ktot - 1) >> 1;          // lower-median rank

        // ranks of temporal candidates in the total order
        // (members before temporal on value ties; prev before next on ties)
        const int rp = cnt_le(lane, prevU, B) + (int)(nextU <  prevU);
        const int rn = cnt_le(lane, nextU, B) + (int)(prevU <= nextU);

        // member-order index of the rank-m element (valid when it's a member)
        const int j = m - (int)(rp < m) - (int)(rn < m);

        // largest position i with (#members at positions < i) <= j  ->  the
        // j-th member's sorted position
        int i = 0;
        #pragma unroll
        for (int st = 64; st > 0; st >>= 1) {
            int c = i + st;                        // <= 127
            const uint4 cm = *((const uint4*)(smem + lane * 516 + c * 4));
            int g = __popc(B.x & cm.x) + __popc(B.y & cm.y)
                  + __popc(B.z & cm.z) + __popc(B.w & cm.w);
            if (g <= j) i = c;
        }

        u32 ans = smem[SORT_BASE + lane * 129 + i];
        if (rn == m) ans = nextU;
        if (rp == m) ans = prevU;

        out[(size_t)bt * (Nc * Dc) + n * Dc + lane] = u2f(ans);
    }
}

extern "C" void kernel_launch(void* const* d_in, const int* in_sizes, int n_in,
                              void* d_out, int out_size)
{
    const float* xs  = (const float*)d_in[0];
    const int*   A   = (const int*)d_in[1];
    float*       out = (float*)d_out;
    (void)in_sizes; (void)n_in; (void)out_size;

    const int dyn = (20640 + 512) * 4;   // 84608 bytes
    cudaFuncSetAttribute(median_kernel,
                         cudaFuncAttributeMaxDynamicSharedMemorySize, dyn);
    cudaFuncSetAttribute(median_kernel,
                         cudaFuncAttributePreferredSharedMemoryCarveout, 100);
    median_kernel<<<Bc * Tc, NTH, dyn>>>(xs, A, out);
}